// round 12
// baseline (speedup 1.0000x reference)
#include <cuda_runtime.h>
#include <math.h>

// Problem shape (fixed by the dataset)
#define T_LEN    4096
#define D_DIM    1024
#define MAX_B    8
#define C_CHUNKS 32
#define L_CHUNK  (T_LEN / C_CHUNKS)   // 128
#define LOG2_L   7                     // L_CHUNK = 2^7

// Scratch (device globals — no allocation in kernel_launch, per harness rules)
__device__ float g_Slocal[MAX_B * C_CHUNKS * D_DIM];        // 1 MB
// Monotonic grid-barrier counter: never reset, so graph replays stay
// deterministic (each launch consumes exactly gridSize increments).
__device__ unsigned long long g_arrive = 0ULL;

// ---------------------------------------------------------------------------
// Single persistent kernel:
//   Phase 1: per-chunk local scan (s_init = 0), stream y_local + Slocal.
//            y stores are evict-first (__stcs): y is write-once, so keep L2
//            capacity for x (128 MB x vs ~126 MB L2; L2 persists across
//            graph replays -> x re-reads can hit L2 if writes don't thrash).
//            launch_bounds(256,2): reg cap 128 so ptxas can front-batch the
//            unroll-16 load stream (deep per-warp MLP).
//   Barrier: all 256 CTAs co-resident (2/SM needed, 2/SM available) ->
//            grid-wide spin barrier is safe.
//   Phase 2: block (j,b) combines preceding chunk states into its incoming
//            state Sin (Horner, multiplier a^L), then applies
//            y[t] += c * a^(t+1) * Sin. Correction is identically zero per
//            channel iff c*a*Sin == 0; zero blocks exit at the barrier.
// ---------------------------------------------------------------------------
__global__ __launch_bounds__(256, 2)
void ssm_onepass(const float* __restrict__ x,
                 const float* __restrict__ logit_a,
                 const float* __restrict__ bvec,
                 const float* __restrict__ cvec,
                 const float* __restrict__ dvec,
                 float* __restrict__ y,
                 int nblk)
{
    const int j  = blockIdx.x;          // chunk
    const int b  = blockIdx.y;          // batch
    const int dc = threadIdx.x * 4;     // channel base

    const float4 la = *reinterpret_cast<const float4*>(logit_a + dc);
    const float4 bb = *reinterpret_cast<const float4*>(bvec + dc);
    const float4 cc = *reinterpret_cast<const float4*>(cvec + dc);
    const float4 dd = *reinterpret_cast<const float4*>(dvec + dc);
    const float ax = tanhf(la.x), ay = tanhf(la.y),
                az = tanhf(la.z), aw = tanhf(la.w);

    // ---------------- Phase 1: local scan + local output ----------------
    float sx = 0.f, sy = 0.f, sz = 0.f, sw = 0.f;

    const size_t base = ((size_t)b * T_LEN + (size_t)j * L_CHUNK) * D_DIM + dc;
    const float4* xp = reinterpret_cast<const float4*>(x + base);
    float4*       yp = reinterpret_cast<float4*>(y + base);
    const int row4 = D_DIM / 4;

    #pragma unroll 16
    for (int t = 0; t < L_CHUNK; ++t) {
        float4 u = xp[(size_t)t * row4];             // normal load: cacheable
        sx = fmaf(ax, sx, bb.x * u.x);
        sy = fmaf(ay, sy, bb.y * u.y);
        sz = fmaf(az, sz, bb.z * u.z);
        sw = fmaf(aw, sw, bb.w * u.w);
        float4 o;
        o.x = fmaf(cc.x, sx, dd.x * u.x);
        o.y = fmaf(cc.y, sy, dd.y * u.y);
        o.z = fmaf(cc.z, sz, dd.z * u.z);
        o.w = fmaf(cc.w, sw, dd.w * u.w);
        __stcs(yp + (size_t)t * row4, o);            // evict-first store
    }

    *reinterpret_cast<float4*>(
        g_Slocal + ((size_t)b * C_CHUNKS + j) * D_DIM + dc)
        = make_float4(sx, sy, sz, sw);

    // ---------------- Grid-wide barrier (monotonic epoch) ----------------
    __threadfence();        // make this thread's Slocal store globally visible
    __syncthreads();        // all threads of the block have fenced
    if (threadIdx.x == 0) {
        unsigned long long old = atomicAdd(&g_arrive, 1ULL);
        unsigned long long target = (old / (unsigned long long)nblk + 1ULL)
                                    * (unsigned long long)nblk;
        while (*((volatile unsigned long long*)&g_arrive) < target) { }
    }
    __syncthreads();
    __threadfence();        // acquire: order subsequent Slocal reads

    // ---------------- Phase 2: carry combine + fix-up ----------------
    // m = a^L via repeated squaring
    float mx = ax, my = ay, mz = az, mw = aw;
    #pragma unroll
    for (int i = 0; i < LOG2_L; ++i) { mx *= mx; my *= my; mz *= mz; mw *= mw; }

    // Sin = Horner combine of preceding chunk-local end states. __ldcg
    // bypasses L1 (other blocks' stores live in L2, written this launch).
    float cx = 0.f, cy = 0.f, cz = 0.f, cw = 0.f;
    const float4* slb = reinterpret_cast<const float4*>(
        g_Slocal + (size_t)b * C_CHUNKS * D_DIM + dc);
    const int q4 = D_DIM / 4;
    #pragma unroll
    for (int i = 0; i < C_CHUNKS - 1; ++i) {
        if (i < j) {
            const float4 sl = __ldcg(slb + (size_t)i * q4);
            cx = fmaf(mx, cx, sl.x);
            cy = fmaf(my, cy, sl.y);
            cz = fmaf(mz, cz, sl.z);
            cw = fmaf(mw, cw, sl.w);
        }
    }

    // first correction term: c * a * Sin ; later terms are this * a^t
    float gx = cc.x * ax * cx, gy = cc.y * ay * cy,
          gz = cc.z * az * cz, gw = cc.w * aw * cw;

    const int mine = (gx != 0.f) | (gy != 0.f) | (gz != 0.f) | (gw != 0.f);
    if (!__syncthreads_or(mine)) return;   // all corrections exactly zero

    #pragma unroll 8
    for (int t = 0; t < L_CHUNK; ++t) {
        float4 o = yp[(size_t)t * row4];
        o.x += gx; o.y += gy; o.z += gz; o.w += gw;   // c * a^(t+1) * Sin
        yp[(size_t)t * row4] = o;
        gx *= ax; gy *= ay; gz *= az; gw *= aw;
    }
}

// ---------------------------------------------------------------------------
// Launch: inputs in metadata order: x, logit_a, b, c, d. Output fp32 (B,T,D).
// ---------------------------------------------------------------------------
extern "C" void kernel_launch(void* const* d_in, const int* in_sizes, int n_in,
                              void* d_out, int out_size)
{
    const float* x  = (const float*)d_in[0];
    const float* la = (const float*)d_in[1];
    const float* bv = (const float*)d_in[2];
    const float* cv = (const float*)d_in[3];
    const float* dv = (const float*)d_in[4];
    float* y = (float*)d_out;

    const int B = in_sizes[0] / (T_LEN * D_DIM);   // = 8

    dim3 grid(C_CHUNKS, B);                        // 256 CTAs, all co-resident
    dim3 blk(256);
    ssm_onepass<<<grid, blk>>>(x, la, bv, cv, dv, y, C_CHUNKS * B);
}

// round 13
// speedup vs baseline: 1.1360x; 1.1360x over previous
#include <cuda_runtime.h>
#include <math.h>

// Problem shape (fixed by the dataset)
#define T_LEN    4096
#define D_DIM    1024
#define MAX_B    8
#define C_CHUNKS 32
#define L_CHUNK  (T_LEN / C_CHUNKS)   // 128
#define LOG2_L   7                     // L_CHUNK = 2^7

// Scratch (device globals — no allocation in kernel_launch, per harness rules)
__device__ float g_Slocal[MAX_B * C_CHUNKS * D_DIM];        // 1 MB
// Monotonic grid-barrier counter: never reset, so graph replays stay
// deterministic (each launch consumes exactly gridSize increments).
__device__ unsigned long long g_arrive = 0ULL;

// ---------------------------------------------------------------------------
// Single kernel, two modes selected by a GRID-UNIFORM predicate:
//
//   need_fix = OR over all channels d of (c_d * tanh(logit_a_d) != 0)
//
// Every block spans the full D=1024 channels, so every block computes the
// same predicate -> either all blocks take the barrier path or none do.
//
//   !need_fix: the cross-chunk correction c*a^(t+1)*Sin is identically zero
//              for every channel (each term carries a factor c*a), so the
//              chunk-local scan IS the answer. Pure 1R+1W stream, no sync.
//   need_fix:  R11-proven generic path: local scan + Slocal, grid-wide
//              monotonic-epoch barrier, Horner carry combine, RMW fix-up.
// ---------------------------------------------------------------------------
__global__ __launch_bounds__(256, 4)
void ssm_onepass(const float* __restrict__ x,
                 const float* __restrict__ logit_a,
                 const float* __restrict__ bvec,
                 const float* __restrict__ cvec,
                 const float* __restrict__ dvec,
                 float* __restrict__ y,
                 int nblk)
{
    const int j  = blockIdx.x;          // chunk
    const int b  = blockIdx.y;          // batch
    const int dc = threadIdx.x * 4;     // channel base

    const float4 la = *reinterpret_cast<const float4*>(logit_a + dc);
    const float4 bb = *reinterpret_cast<const float4*>(bvec + dc);
    const float4 cc = *reinterpret_cast<const float4*>(cvec + dc);
    const float4 dd = *reinterpret_cast<const float4*>(dvec + dc);
    const float ax = tanhf(la.x), ay = tanhf(la.y),
                az = tanhf(la.z), aw = tanhf(la.w);

    // Grid-uniform predicate: does any channel need a cross-chunk fix?
    const int mine_ca = (cc.x * ax != 0.f) | (cc.y * ay != 0.f) |
                        (cc.z * az != 0.f) | (cc.w * aw != 0.f);
    const int need_fix = __syncthreads_or(mine_ca);

    const size_t base = ((size_t)b * T_LEN + (size_t)j * L_CHUNK) * D_DIM + dc;
    const float4* xp = reinterpret_cast<const float4*>(x + base);
    float4*       yp = reinterpret_cast<float4*>(y + base);
    const int row4 = D_DIM / 4;

    float sx = 0.f, sy = 0.f, sz = 0.f, sw = 0.f;

    if (!need_fix) {
        // ---------- Lean path: local scan is exact; pure streaming ----------
        #pragma unroll 8
        for (int t = 0; t < L_CHUNK; ++t) {
            float4 u = xp[(size_t)t * row4];
            sx = fmaf(ax, sx, bb.x * u.x);
            sy = fmaf(ay, sy, bb.y * u.y);
            sz = fmaf(az, sz, bb.z * u.z);
            sw = fmaf(aw, sw, bb.w * u.w);
            float4 o;
            o.x = fmaf(cc.x, sx, dd.x * u.x);
            o.y = fmaf(cc.y, sy, dd.y * u.y);
            o.z = fmaf(cc.z, sz, dd.z * u.z);
            o.w = fmaf(cc.w, sw, dd.w * u.w);
            yp[(size_t)t * row4] = o;
        }
        return;
    }

    // ---------------- Generic path (R11): phase 1 ----------------
    #pragma unroll 8
    for (int t = 0; t < L_CHUNK; ++t) {
        float4 u = xp[(size_t)t * row4];
        sx = fmaf(ax, sx, bb.x * u.x);
        sy = fmaf(ay, sy, bb.y * u.y);
        sz = fmaf(az, sz, bb.z * u.z);
        sw = fmaf(aw, sw, bb.w * u.w);
        float4 o;
        o.x = fmaf(cc.x, sx, dd.x * u.x);
        o.y = fmaf(cc.y, sy, dd.y * u.y);
        o.z = fmaf(cc.z, sz, dd.z * u.z);
        o.w = fmaf(cc.w, sw, dd.w * u.w);
        yp[(size_t)t * row4] = o;
    }

    *reinterpret_cast<float4*>(
        g_Slocal + ((size_t)b * C_CHUNKS + j) * D_DIM + dc)
        = make_float4(sx, sy, sz, sw);

    // Grid-wide barrier (monotonic epoch; all 256 CTAs co-resident)
    __threadfence();
    __syncthreads();
    if (threadIdx.x == 0) {
        unsigned long long old = atomicAdd(&g_arrive, 1ULL);
        unsigned long long target = (old / (unsigned long long)nblk + 1ULL)
                                    * (unsigned long long)nblk;
        while (*((volatile unsigned long long*)&g_arrive) < target) { }
    }
    __syncthreads();
    __threadfence();

    // Phase 2: carry combine + fix-up
    float mx = ax, my = ay, mz = az, mw = aw;
    #pragma unroll
    for (int i = 0; i < LOG2_L; ++i) { mx *= mx; my *= my; mz *= mz; mw *= mw; }

    float cx = 0.f, cy = 0.f, cz = 0.f, cw = 0.f;
    const float4* slb = reinterpret_cast<const float4*>(
        g_Slocal + (size_t)b * C_CHUNKS * D_DIM + dc);
    const int q4 = D_DIM / 4;
    #pragma unroll
    for (int i = 0; i < C_CHUNKS - 1; ++i) {
        if (i < j) {
            const float4 sl = __ldcg(slb + (size_t)i * q4);
            cx = fmaf(mx, cx, sl.x);
            cy = fmaf(my, cy, sl.y);
            cz = fmaf(mz, cz, sl.z);
            cw = fmaf(mw, cw, sl.w);
        }
    }

    float gx = cc.x * ax * cx, gy = cc.y * ay * cy,
          gz = cc.z * az * cz, gw = cc.w * aw * cw;

    const int mine = (gx != 0.f) | (gy != 0.f) | (gz != 0.f) | (gw != 0.f);
    if (!__syncthreads_or(mine)) return;   // this chunk's corrections all zero

    #pragma unroll 8
    for (int t = 0; t < L_CHUNK; ++t) {
        float4 o = yp[(size_t)t * row4];
        o.x += gx; o.y += gy; o.z += gz; o.w += gw;   // c * a^(t+1) * Sin
        yp[(size_t)t * row4] = o;
        gx *= ax; gy *= ay; gz *= az; gw *= aw;
    }
}

// ---------------------------------------------------------------------------
// Launch: inputs in metadata order: x, logit_a, b, c, d. Output fp32 (B,T,D).
// ---------------------------------------------------------------------------
extern "C" void kernel_launch(void* const* d_in, const int* in_sizes, int n_in,
                              void* d_out, int out_size)
{
    const float* x  = (const float*)d_in[0];
    const float* la = (const float*)d_in[1];
    const float* bv = (const float*)d_in[2];
    const float* cv = (const float*)d_in[3];
    const float* dv = (const float*)d_in[4];
    float* y = (float*)d_out;

    const int B = in_sizes[0] / (T_LEN * D_DIM);   // = 8

    dim3 grid(C_CHUNKS, B);                        // 256 CTAs, all co-resident
    dim3 blk(256);
    ssm_onepass<<<grid, blk>>>(x, la, bv, cv, dv, y, C_CHUNKS * B);
}